// round 10
// baseline (speedup 1.0000x reference)
#include <cuda_runtime.h>
#include <cuda_bf16.h>
#include <math.h>
#include <stdint.h>

#define B_ROWS   4096
#define T_LEN    256
#define NROWS    (B_ROWS * 64)
#define NFFT     24
#define FBINS    12
#define DIN      256
#define FEAT     512
#define K1P      (3 * DIN)     // 768
#define K2P      (3 * FEAT)    // 1536

// ---------------- scratch (__device__ globals; no allocs) ----------------
__device__ __nv_bfloat16 g_a1[B_ROWS * K1P];    // [Ah | Ah | Al]      6 MB
__device__ __nv_bfloat16 g_h2[B_ROWS * K2P];    // [Hh | Hh | Hl]     12 MB
__device__ __nv_bfloat16 g_w1t[FEAT * K1P];     // [W1h | W1l | W1h]^T
__device__ __nv_bfloat16 g_w2t[FEAT * K2P];     // [W2h | W2l | W2h]^T

// ---------------- helpers ----------------
__device__ __forceinline__ uint32_t smem_u32(const void* p) {
    uint32_t a;
    asm("{ .reg .u64 t; cvta.to.shared.u64 t, %1; cvt.u32.u64 %0, t; }"
        : "=r"(a) : "l"(p));
    return a;
}
__device__ __forceinline__ void cp16(uint32_t dst, const void* src) {
    asm volatile("cp.async.cg.shared.global [%0], [%1], 16;"
                 :: "r"(dst), "l"(src));
}
__device__ __forceinline__ void cp_commit() {
    asm volatile("cp.async.commit_group;");
}
template <int N>
__device__ __forceinline__ void cp_wait() {
    asm volatile("cp.async.wait_group %0;" :: "n"(N));
}
#define LDSM4(r, addr)                                                        \
    asm volatile("ldmatrix.sync.aligned.m8n8.x4.shared.b16 {%0,%1,%2,%3}, [%4];" \
                 : "=r"((r)[0]), "=r"((r)[1]), "=r"((r)[2]), "=r"((r)[3])     \
                 : "r"(addr))
#define MMA16816(d, a, b0, b1)                                                \
    asm volatile(                                                             \
        "mma.sync.aligned.m16n8k16.row.col.f32.bf16.bf16.f32 "                \
        "{%0,%1,%2,%3}, {%4,%5,%6,%7}, {%8,%9}, {%0,%1,%2,%3};"               \
        : "+f"((d)[0]), "+f"((d)[1]), "+f"((d)[2]), "+f"((d)[3])              \
        : "r"((a)[0]), "r"((a)[1]), "r"((a)[2]), "r"((a)[3]),                 \
          "r"(b0), "r"(b1))

// packed fp32x2 helpers
__device__ __forceinline__ unsigned long long pack2(float lo, float hi) {
    unsigned long long r;
    asm("mov.b64 %0, {%1, %2};" : "=l"(r) : "f"(lo), "f"(hi));
    return r;
}
__device__ __forceinline__ void fma2(unsigned long long& d,
                                     unsigned long long a, unsigned long long b) {
    asm("fma.rn.f32x2 %0, %1, %2, %0;" : "+l"(d) : "l"(a), "l"(b));
}
__device__ __forceinline__ float2 unpack2(unsigned long long v) {
    float2 r;
    asm("mov.b64 {%0, %1}, %2;" : "=f"(r.x), "=f"(r.y) : "l"(v));
    return r;
}
__device__ __forceinline__ float gelu_exact(float v) {
    return 0.5f * v * (1.0f + erff(v * 0.70710678118654752f));
}
__device__ __forceinline__ void split_bf16(float v, __nv_bfloat16& h, __nv_bfloat16& l) {
    h = __float2bfloat16_rn(v);
    l = __float2bfloat16_rn(v - __bfloat162float(h));
}

// ---------------------------------------------------------------------------
// Kernel 1: spectral features -> A' = [Ah | Ah | Al]  [4096 x 768] bf16
// ---------------------------------------------------------------------------
__global__ __launch_bounds__(256) void feats_kernel(
    const float* __restrict__ x, __nv_bfloat16* __restrict__ a1)
{
    __shared__ float2 s_tw[NFFT];
    int t = threadIdx.x;
    if (t < NFFT) {
        float s, c;
        sincospif((float)t / 12.0f, &s, &c);
        s_tw[t] = make_float2(c, -s);
    }
    __syncthreads();

    int row = blockIdx.x * 256 + t;

    unsigned long long tw[NFFT];
#pragma unroll
    for (int m = 0; m < NFFT; m++) { float2 v = s_tw[m]; tw[m] = pack2(v.x, v.y); }

    const float4* xp = reinterpret_cast<const float4*>(x + (size_t)row * T_LEN);
    float xs[NFFT];
#pragma unroll
    for (int i = 0; i < 6; i++) {
        float4 v = xp[i];
        xs[4*i + 0] = v.x; xs[4*i + 1] = v.y;
        xs[4*i + 2] = v.z; xs[4*i + 3] = v.w;
    }

    unsigned long long acc[FBINS];
#pragma unroll
    for (int k = 0; k < FBINS; k++) acc[k] = pack2(0.f, 0.f);
#pragma unroll
    for (int n = 0; n < NFFT; n++) {
        unsigned long long xv = pack2(xs[n], xs[n]);
#pragma unroll
        for (int k = 1; k <= FBINS; k++) {
            const int m = (k * n) % NFFT;
            fma2(acc[k-1], xv, tw[m]);
        }
    }

    float re[FBINS], im[FBINS], mag2[FBINS];
#pragma unroll
    for (int k = 0; k < FBINS; k++) {
        float2 p = unpack2(acc[k]);
        re[k] = p.x; im[k] = p.y;
        mag2[k] = p.x*p.x + p.y*p.y;
    }

    int i1 = 0; float m1 = mag2[0];
#pragma unroll
    for (int k = 1; k < FBINS; k++) if (mag2[k] > m1) { m1 = mag2[k]; i1 = k; }
    int i2 = (i1 == 0) ? 1 : 0; float m2 = mag2[i2];
#pragma unroll
    for (int k = 0; k < FBINS; k++)
        if (k != i1 && mag2[k] > m2) { m2 = mag2[k]; i2 = k; }

    float r1 = 0.f, q1 = 0.f, r2 = 0.f, q2 = 0.f;
#pragma unroll
    for (int k = 0; k < FBINS; k++) {
        if (k == i1) { r1 = re[k]; q1 = im[k]; }
        if (k == i2) { r2 = re[k]; q2 = im[k]; }
    }

    float o0 = sqrtf(m1);
    float o1 = sqrtf(m2);
    float o2 = atan2f(q1, r1);
    float o3 = atan2f(q2, r2);

    __nv_bfloat16 h0,h1,h2,h3,l0,l1,l2,l3;
    split_bf16(o0,h0,l0); split_bf16(o1,h1,l1);
    split_bf16(o2,h2,l2); split_bf16(o3,h3,l3);

    int b = row >> 6, c = row & 63;
    __nv_bfloat16* base = a1 + (size_t)b * K1P + c * 4;
    __nv_bfloat162 hp0{h0, h1}, hp1{h2, h3}, lp0{l0, l1}, lp1{l2, l3};
    reinterpret_cast<__nv_bfloat162*>(base)[0]         = hp0;
    reinterpret_cast<__nv_bfloat162*>(base)[1]         = hp1;
    reinterpret_cast<__nv_bfloat162*>(base + DIN)[0]   = hp0;
    reinterpret_cast<__nv_bfloat162*>(base + DIN)[1]   = hp1;
    reinterpret_cast<__nv_bfloat162*>(base + 2*DIN)[0] = lp0;
    reinterpret_cast<__nv_bfloat162*>(base + 2*DIN)[1] = lp1;
}

// ---------------------------------------------------------------------------
// W prep: W[K][N] fp32 -> Wt'[N][3K] bf16 layout [Wh | Wl | Wh] per row
// ---------------------------------------------------------------------------
__global__ __launch_bounds__(256) void prep_w(
    const float* __restrict__ W, __nv_bfloat16* __restrict__ Tp, int K, int N)
{
    __shared__ float sm[32][33];
    int k0 = blockIdx.y * 32, n0 = blockIdx.x * 32;
    int tx = threadIdx.x & 31, ty = threadIdx.x >> 5;
#pragma unroll
    for (int i = ty; i < 32; i += 8)
        sm[i][tx] = W[(size_t)(k0 + i) * N + n0 + tx];
    __syncthreads();
#pragma unroll
    for (int r = ty; r < 32; r += 8) {
        float v = sm[tx][r];
        __nv_bfloat16 h, l; split_bf16(v, h, l);
        size_t rb = (size_t)(n0 + r) * (3 * K);
        Tp[rb + k0 + tx]         = h;
        Tp[rb + K + k0 + tx]     = l;
        Tp[rb + 2 * K + k0 + tx] = h;
    }
}

// ---------------------------------------------------------------------------
// bf16 HMMA GEMM: CTA 128x128, 512 threads, 16 warps of 32x32,
// KC=64 (4 k16 phases/stage), 4-stage cp.async ring, frag double-buffering.
// Grid (4, 32) = 128 CTAs, 1 CTA/SM, 16 warps/SM (4 per SMSP).
// ---------------------------------------------------------------------------
#define GT      512
#define KPAD    72                        // elems per smem row (144 B)
#define A_ELS   (128 * KPAD)              // 9216 elems
#define STGB    (2 * A_ELS * 2)           // A + B, 36864 B
#define B_OFF   (A_ELS * 2)
#define NSTAGE  4
#define SMEM_BYTES (NSTAGE * STGB)        // 147456

template <int KTOT, bool SPLIT_OUT>
__global__ __launch_bounds__(GT, 1) void hmma_gemm(
    const __nv_bfloat16* __restrict__ A, const __nv_bfloat16* __restrict__ Bt,
    const float* __restrict__ bias,
    float* __restrict__ outF, __nv_bfloat16* __restrict__ outS)
{
    extern __shared__ __nv_bfloat16 sm[];

    const int tid  = threadIdx.x;
    const int lane = tid & 31;
    const int wid  = tid >> 5;
    const int brow = blockIdx.y * 128;
    const int bcol = blockIdx.x * 128;
    const int m0 = (wid & 3) * 32;        // 4 warps in m
    const int n0 = (wid >> 2) * 32;       // 4 warps in n

    // ---- copy setup: stage = 128 rows x 64 elems for A and B (1024 chunks ea).
    // 512 threads x 2 chunks each.
    const __nv_bfloat16* gAp[2];
    const __nv_bfloat16* gBp[2];
    uint32_t sAo[2], sBo[2];
#pragma unroll
    for (int i = 0; i < 2; i++) {
        int u = i * GT + tid;
        int r = u >> 3, ch = u & 7;
        gAp[i] = A  + (size_t)(brow + r) * KTOT + ch * 8;
        gBp[i] = Bt + (size_t)(bcol + r) * KTOT + ch * 8;
        sAo[i] = smem_u32(sm) + (uint32_t)(r * KPAD * 2 + ch * 16);
        sBo[i] = sAo[i] + B_OFF;
    }

    auto copy_tile = [&](int kt, int slot) {
        const uint32_t so = slot * STGB;
        const int ko = kt * 64;
#pragma unroll
        for (int i = 0; i < 2; i++) cp16(sAo[i] + so, gAp[i] + ko);
#pragma unroll
        for (int i = 0; i < 2; i++) cp16(sBo[i] + so, gBp[i] + ko);
    };

    constexpr int NT = KTOT / 64;

    // prologue: fill stages 0..2
#pragma unroll
    for (int p = 0; p < NSTAGE - 1; p++) {
        copy_tile(p, p);
        cp_commit();
    }

    float c[2][4][4];
#pragma unroll
    for (int i = 0; i < 2; i++)
#pragma unroll
        for (int j = 0; j < 4; j++)
#pragma unroll
            for (int q = 0; q < 4; q++) c[i][j][q] = 0.0f;

    // ldmatrix lane addressing
    const int a_row = lane & 15;
    const int a_kh  = (lane >> 4) * 8;
    const int b_row = (lane & 7) + ((lane >> 4) << 3);
    const int b_kh  = ((lane >> 3) & 1) << 3;

    uint32_t aAddr[2], bAddr[2];
#pragma unroll
    for (int i = 0; i < 2; i++)
        aAddr[i] = smem_u32(&sm[(m0 + i * 16 + a_row) * KPAD + a_kh]);
#pragma unroll
    for (int j = 0; j < 2; j++)
        bAddr[j] = smem_u32(sm) + B_OFF +
                   (uint32_t)(((n0 + j * 16 + b_row) * KPAD + b_kh) * 2);

    // double-buffered fragments
    uint32_t aF[2][2][4], bF[2][2][4];

    // preamble: stage 0 ready; preload phase 0 into buf 0
    cp_wait<NSTAGE - 2>();
    __syncthreads();
#pragma unroll
    for (int i = 0; i < 2; i++) LDSM4(aF[0][i], aAddr[i]);
#pragma unroll
    for (int j = 0; j < 2; j++) LDSM4(bF[0][j], bAddr[j]);

    for (int kt = 0; kt < NT; kt++) {
        const uint32_t so  = (kt % NSTAGE) * STGB;
        const uint32_t so1 = ((kt + 1) % NSTAGE) * STGB;

#pragma unroll
        for (int ks = 0; ks < 4; ks++) {
            const int cb = ks & 1, nb = cb ^ 1;
            if (ks < 3) {
                const uint32_t po = so + (ks + 1) * 32;
#pragma unroll
                for (int i = 0; i < 2; i++) LDSM4(aF[nb][i], aAddr[i] + po);
#pragma unroll
                for (int j = 0; j < 2; j++) LDSM4(bF[nb][j], bAddr[j] + po);
            }
            if (ks == 1) {
                const int nk = kt + NSTAGE - 1;
                if (nk < NT) copy_tile(nk, nk % NSTAGE);
                cp_commit();
            }
            if (ks == 3) {
                cp_wait<NSTAGE - 2>();
                __syncthreads();
            }
#pragma unroll
            for (int i = 0; i < 2; i++)
#pragma unroll
                for (int jn = 0; jn < 4; jn++) {
                    const int j = jn >> 1;
                    if (jn & 1) MMA16816(c[i][jn], aF[cb][i], bF[cb][j][2], bF[cb][j][3]);
                    else        MMA16816(c[i][jn], aF[cb][i], bF[cb][j][0], bF[cb][j][1]);
                }
        }

        // preload phase 0 of stage kt+1 into buf 0
        if (kt + 1 < NT) {
#pragma unroll
            for (int i = 0; i < 2; i++) LDSM4(aF[0][i], aAddr[i] + so1);
#pragma unroll
            for (int j = 0; j < 2; j++) LDSM4(bF[0][j], bAddr[j] + so1);
        }
    }

    // ---- epilogue ----
#pragma unroll
    for (int i = 0; i < 2; i++) {
        const int gm = brow + m0 + i * 16 + (lane >> 2);
#pragma unroll
        for (int jn = 0; jn < 4; jn++) {
            const int gc = bcol + n0 + jn * 8 + ((lane & 3) << 1);
            float2 bb = *reinterpret_cast<const float2*>(bias + gc);
#pragma unroll
            for (int rh = 0; rh < 2; rh++) {
                const int m = gm + rh * 8;
                float v0 = c[i][jn][rh * 2 + 0] + bb.x;
                float v1 = c[i][jn][rh * 2 + 1] + bb.y;
                if (SPLIT_OUT) {
                    v0 = gelu_exact(v0);
                    v1 = gelu_exact(v1);
                    __nv_bfloat16 h0,l0,h1,l1;
                    split_bf16(v0, h0, l0); split_bf16(v1, h1, l1);
                    __nv_bfloat162 hp{h0, h1}, lp{l0, l1};
                    __nv_bfloat16* ro = outS + (size_t)m * K2P + gc;
                    *reinterpret_cast<__nv_bfloat162*>(ro)          = hp;
                    *reinterpret_cast<__nv_bfloat162*>(ro + FEAT)   = hp;
                    *reinterpret_cast<__nv_bfloat162*>(ro + 2*FEAT) = lp;
                } else {
                    float2 o{v0, v1};
                    *reinterpret_cast<float2*>(outF + (size_t)m * FEAT + gc) = o;
                }
            }
        }
    }
}

// ---------------------------------------------------------------------------
extern "C" void kernel_launch(void* const* d_in, const int* in_sizes, int n_in,
                              void* d_out, int out_size)
{
    const float* x  = (const float*)d_in[0];
    const float* W1 = (const float*)d_in[1];
    const float* b1 = (const float*)d_in[2];
    const float* W2 = (const float*)d_in[3];
    const float* b2 = (const float*)d_in[4];
    float* out = (float*)d_out;

    __nv_bfloat16 *a1, *h2, *w1t, *w2t;
    cudaGetSymbolAddress((void**)&a1,  g_a1);
    cudaGetSymbolAddress((void**)&h2,  g_h2);
    cudaGetSymbolAddress((void**)&w1t, g_w1t);
    cudaGetSymbolAddress((void**)&w2t, g_w2t);

    cudaFuncSetAttribute(hmma_gemm<K1P, true>,
                         cudaFuncAttributeMaxDynamicSharedMemorySize, SMEM_BYTES);
    cudaFuncSetAttribute(hmma_gemm<K2P, false>,
                         cudaFuncAttributeMaxDynamicSharedMemorySize, SMEM_BYTES);

    prep_w<<<dim3(FEAT / 32, DIN / 32),  256>>>(W1, w1t, DIN,  FEAT);
    prep_w<<<dim3(FEAT / 32, FEAT / 32), 256>>>(W2, w2t, FEAT, FEAT);
    feats_kernel<<<NROWS / 256, 256>>>(x, a1);

    dim3 grid(FEAT / 128, B_ROWS / 128);   // (4, 32) = 128 CTAs
    hmma_gemm<K1P, true ><<<grid, GT, SMEM_BYTES>>>(a1, w1t, b1, nullptr, h2);
    hmma_gemm<K2P, false><<<grid, GT, SMEM_BYTES>>>(h2, w2t, b2, out, nullptr);
}

// round 11
// speedup vs baseline: 1.2326x; 1.2326x over previous
#include <cuda_runtime.h>
#include <cuda_fp16.h>
#include <math.h>
#include <stdint.h>

#define B_ROWS   4096
#define T_LEN    256
#define NROWS    (B_ROWS * 64)
#define NFFT     24
#define FBINS    12
#define DIN      256
#define FEAT     512
#define K1F      (2 * DIN)     // 512  : [Ah | Al] . [Wh | Wh]
#define K2F      (2 * FEAT)    // 1024 : [Hh | Hl] . [Wh | Wh]

// ---------------- scratch (__device__ globals; no allocs) ----------------
__device__ __half g_a1[B_ROWS * K1F];     // [Ah | Al]          4 MB
__device__ __half g_h2[B_ROWS * K2F];     // [Hh | Hl]          8 MB
__device__ __half g_w1t[FEAT * K1F];      // [W1h | W1h]^T
__device__ __half g_w2t[FEAT * K2F];      // [W2h | W2h]^T

// ---------------- helpers ----------------
__device__ __forceinline__ uint32_t smem_u32(const void* p) {
    uint32_t a;
    asm("{ .reg .u64 t; cvta.to.shared.u64 t, %1; cvt.u32.u64 %0, t; }"
        : "=r"(a) : "l"(p));
    return a;
}
__device__ __forceinline__ void cp16(uint32_t dst, const void* src) {
    asm volatile("cp.async.cg.shared.global [%0], [%1], 16;"
                 :: "r"(dst), "l"(src));
}
__device__ __forceinline__ void cp_commit() {
    asm volatile("cp.async.commit_group;");
}
template <int N>
__device__ __forceinline__ void cp_wait() {
    asm volatile("cp.async.wait_group %0;" :: "n"(N));
}
#define LDSM4(r, addr)                                                        \
    asm volatile("ldmatrix.sync.aligned.m8n8.x4.shared.b16 {%0,%1,%2,%3}, [%4];" \
                 : "=r"((r)[0]), "=r"((r)[1]), "=r"((r)[2]), "=r"((r)[3])     \
                 : "r"(addr))
#define MMA16816(d, a, b0, b1)                                                \
    asm volatile(                                                             \
        "mma.sync.aligned.m16n8k16.row.col.f32.f16.f16.f32 "                  \
        "{%0,%1,%2,%3}, {%4,%5,%6,%7}, {%8,%9}, {%0,%1,%2,%3};"               \
        : "+f"((d)[0]), "+f"((d)[1]), "+f"((d)[2]), "+f"((d)[3])              \
        : "r"((a)[0]), "r"((a)[1]), "r"((a)[2]), "r"((a)[3]),                 \
          "r"(b0), "r"(b1))

// packed fp32x2 helpers
__device__ __forceinline__ unsigned long long pack2(float lo, float hi) {
    unsigned long long r;
    asm("mov.b64 %0, {%1, %2};" : "=l"(r) : "f"(lo), "f"(hi));
    return r;
}
__device__ __forceinline__ void fma2(unsigned long long& d,
                                     unsigned long long a, unsigned long long b) {
    asm("fma.rn.f32x2 %0, %1, %2, %0;" : "+l"(d) : "l"(a), "l"(b));
}
__device__ __forceinline__ float2 unpack2(unsigned long long v) {
    float2 r;
    asm("mov.b64 {%0, %1}, %2;" : "=f"(r.x), "=f"(r.y) : "l"(v));
    return r;
}
__device__ __forceinline__ float gelu_exact(float v) {
    return 0.5f * v * (1.0f + erff(v * 0.70710678118654752f));
}
__device__ __forceinline__ void split_f16(float v, __half& h, __half& l) {
    h = __float2half_rn(v);
    l = __float2half_rn(v - __half2float(h));
}

// ---------------------------------------------------------------------------
// Kernel 1: spectral features -> A' = [Ah | Al]  [4096 x 512] fp16
// ---------------------------------------------------------------------------
__global__ __launch_bounds__(256) void feats_kernel(
    const float* __restrict__ x, __half* __restrict__ a1)
{
    __shared__ float2 s_tw[NFFT];
    int t = threadIdx.x;
    if (t < NFFT) {
        float s, c;
        sincospif((float)t / 12.0f, &s, &c);
        s_tw[t] = make_float2(c, -s);
    }
    __syncthreads();

    int row = blockIdx.x * 256 + t;

    unsigned long long tw[NFFT];
#pragma unroll
    for (int m = 0; m < NFFT; m++) { float2 v = s_tw[m]; tw[m] = pack2(v.x, v.y); }

    const float4* xp = reinterpret_cast<const float4*>(x + (size_t)row * T_LEN);
    float xs[NFFT];
#pragma unroll
    for (int i = 0; i < 6; i++) {
        float4 v = xp[i];
        xs[4*i + 0] = v.x; xs[4*i + 1] = v.y;
        xs[4*i + 2] = v.z; xs[4*i + 3] = v.w;
    }

    unsigned long long acc[FBINS];
#pragma unroll
    for (int k = 0; k < FBINS; k++) acc[k] = pack2(0.f, 0.f);
#pragma unroll
    for (int n = 0; n < NFFT; n++) {
        unsigned long long xv = pack2(xs[n], xs[n]);
#pragma unroll
        for (int k = 1; k <= FBINS; k++) {
            const int m = (k * n) % NFFT;
            fma2(acc[k-1], xv, tw[m]);
        }
    }

    float re[FBINS], im[FBINS], mag2[FBINS];
#pragma unroll
    for (int k = 0; k < FBINS; k++) {
        float2 p = unpack2(acc[k]);
        re[k] = p.x; im[k] = p.y;
        mag2[k] = p.x*p.x + p.y*p.y;
    }

    int i1 = 0; float m1 = mag2[0];
#pragma unroll
    for (int k = 1; k < FBINS; k++) if (mag2[k] > m1) { m1 = mag2[k]; i1 = k; }
    int i2 = (i1 == 0) ? 1 : 0; float m2 = mag2[i2];
#pragma unroll
    for (int k = 0; k < FBINS; k++)
        if (k != i1 && mag2[k] > m2) { m2 = mag2[k]; i2 = k; }

    float r1 = 0.f, q1 = 0.f, r2 = 0.f, q2 = 0.f;
#pragma unroll
    for (int k = 0; k < FBINS; k++) {
        if (k == i1) { r1 = re[k]; q1 = im[k]; }
        if (k == i2) { r2 = re[k]; q2 = im[k]; }
    }

    float o0 = sqrtf(m1);
    float o1 = sqrtf(m2);
    float o2 = atan2f(q1, r1);
    float o3 = atan2f(q2, r2);

    __half h0,h1,h2,h3,l0,l1,l2,l3;
    split_f16(o0,h0,l0); split_f16(o1,h1,l1);
    split_f16(o2,h2,l2); split_f16(o3,h3,l3);

    int b = row >> 6, c = row & 63;
    __half* base = a1 + (size_t)b * K1F + c * 4;
    reinterpret_cast<__half2*>(base)[0]       = __halves2half2(h0, h1);
    reinterpret_cast<__half2*>(base)[1]       = __halves2half2(h2, h3);
    reinterpret_cast<__half2*>(base + DIN)[0] = __halves2half2(l0, l1);
    reinterpret_cast<__half2*>(base + DIN)[1] = __halves2half2(l2, l3);
}

// ---------------------------------------------------------------------------
// W prep: W[K][N] fp32 -> Wt'[N][2K] fp16 layout [Wh | Wh] per row
// ---------------------------------------------------------------------------
__global__ __launch_bounds__(256) void prep_w(
    const float* __restrict__ W, __half* __restrict__ Tp, int K, int N)
{
    __shared__ float sm[32][33];
    int k0 = blockIdx.y * 32, n0 = blockIdx.x * 32;
    int tx = threadIdx.x & 31, ty = threadIdx.x >> 5;
#pragma unroll
    for (int i = ty; i < 32; i += 8)
        sm[i][tx] = W[(size_t)(k0 + i) * N + n0 + tx];
    __syncthreads();
#pragma unroll
    for (int r = ty; r < 32; r += 8) {
        __half h = __float2half_rn(sm[tx][r]);
        size_t rb = (size_t)(n0 + r) * (2 * K);
        Tp[rb + k0 + tx]     = h;
        Tp[rb + K + k0 + tx] = h;
    }
}

// ---------------------------------------------------------------------------
// fp16 HMMA GEMM: CTA 128x128, 512 threads, 16 warps of 32x32,
// KC=64 (4 k16 phases/stage), 4-stage cp.async ring, frag double-buffering.
// Grid (4, 32) = 128 CTAs, 1 CTA/SM.
// ---------------------------------------------------------------------------
#define GT      512
#define KPAD    72
#define A_ELS   (128 * KPAD)
#define STGB    (2 * A_ELS * 2)
#define B_OFF   (A_ELS * 2)
#define NSTAGE  4
#define SMEM_BYTES (NSTAGE * STGB)        // 147456

template <int KTOT, bool SPLIT_OUT>
__global__ __launch_bounds__(GT, 1) void hmma_gemm(
    const __half* __restrict__ A, const __half* __restrict__ Bt,
    const float* __restrict__ bias,
    float* __restrict__ outF, __half* __restrict__ outS)
{
    extern __shared__ __half sm[];

    const int tid  = threadIdx.x;
    const int lane = tid & 31;
    const int wid  = tid >> 5;
    const int brow = blockIdx.y * 128;
    const int bcol = blockIdx.x * 128;
    const int m0 = (wid & 3) * 32;
    const int n0 = (wid >> 2) * 32;

    const __half* gAp[2];
    const __half* gBp[2];
    uint32_t sAo[2], sBo[2];
#pragma unroll
    for (int i = 0; i < 2; i++) {
        int u = i * GT + tid;
        int r = u >> 3, ch = u & 7;
        gAp[i] = A  + (size_t)(brow + r) * KTOT + ch * 8;
        gBp[i] = Bt + (size_t)(bcol + r) * KTOT + ch * 8;
        sAo[i] = smem_u32(sm) + (uint32_t)(r * KPAD * 2 + ch * 16);
        sBo[i] = sAo[i] + B_OFF;
    }

    auto copy_tile = [&](int kt, int slot) {
        const uint32_t so = slot * STGB;
        const int ko = kt * 64;
#pragma unroll
        for (int i = 0; i < 2; i++) cp16(sAo[i] + so, gAp[i] + ko);
#pragma unroll
        for (int i = 0; i < 2; i++) cp16(sBo[i] + so, gBp[i] + ko);
    };

    constexpr int NT = KTOT / 64;

#pragma unroll
    for (int p = 0; p < NSTAGE - 1; p++) {
        copy_tile(p, p);
        cp_commit();
    }

    float c[2][4][4];
#pragma unroll
    for (int i = 0; i < 2; i++)
#pragma unroll
        for (int j = 0; j < 4; j++)
#pragma unroll
            for (int q = 0; q < 4; q++) c[i][j][q] = 0.0f;

    const int a_row = lane & 15;
    const int a_kh  = (lane >> 4) * 8;
    const int b_row = (lane & 7) + ((lane >> 4) << 3);
    const int b_kh  = ((lane >> 3) & 1) << 3;

    uint32_t aAddr[2], bAddr[2];
#pragma unroll
    for (int i = 0; i < 2; i++)
        aAddr[i] = smem_u32(&sm[(m0 + i * 16 + a_row) * KPAD + a_kh]);
#pragma unroll
    for (int j = 0; j < 2; j++)
        bAddr[j] = smem_u32(sm) + B_OFF +
                   (uint32_t)(((n0 + j * 16 + b_row) * KPAD + b_kh) * 2);

    uint32_t aF[2][2][4], bF[2][2][4];

    cp_wait<NSTAGE - 2>();
    __syncthreads();
#pragma unroll
    for (int i = 0; i < 2; i++) LDSM4(aF[0][i], aAddr[i]);
#pragma unroll
    for (int j = 0; j < 2; j++) LDSM4(bF[0][j], bAddr[j]);

    for (int kt = 0; kt < NT; kt++) {
        const uint32_t so  = (kt % NSTAGE) * STGB;
        const uint32_t so1 = ((kt + 1) % NSTAGE) * STGB;

#pragma unroll
        for (int ks = 0; ks < 4; ks++) {
            const int cb = ks & 1, nb = cb ^ 1;
            if (ks < 3) {
                const uint32_t po = so + (ks + 1) * 32;
#pragma unroll
                for (int i = 0; i < 2; i++) LDSM4(aF[nb][i], aAddr[i] + po);
#pragma unroll
                for (int j = 0; j < 2; j++) LDSM4(bF[nb][j], bAddr[j] + po);
            }
            if (ks == 1) {
                const int nk = kt + NSTAGE - 1;
                if (nk < NT) copy_tile(nk, nk % NSTAGE);
                cp_commit();
            }
            if (ks == 3) {
                cp_wait<NSTAGE - 2>();
                __syncthreads();
            }
#pragma unroll
            for (int i = 0; i < 2; i++)
#pragma unroll
                for (int jn = 0; jn < 4; jn++) {
                    const int j = jn >> 1;
                    if (jn & 1) MMA16816(c[i][jn], aF[cb][i], bF[cb][j][2], bF[cb][j][3]);
                    else        MMA16816(c[i][jn], aF[cb][i], bF[cb][j][0], bF[cb][j][1]);
                }
        }

        if (kt + 1 < NT) {
#pragma unroll
            for (int i = 0; i < 2; i++) LDSM4(aF[0][i], aAddr[i] + so1);
#pragma unroll
            for (int j = 0; j < 2; j++) LDSM4(bF[0][j], bAddr[j] + so1);
        }
    }

    // ---- epilogue ----
#pragma unroll
    for (int i = 0; i < 2; i++) {
        const int gm = brow + m0 + i * 16 + (lane >> 2);
#pragma unroll
        for (int jn = 0; jn < 4; jn++) {
            const int gc = bcol + n0 + jn * 8 + ((lane & 3) << 1);
            float2 bb = *reinterpret_cast<const float2*>(bias + gc);
#pragma unroll
            for (int rh = 0; rh < 2; rh++) {
                const int m = gm + rh * 8;
                float v0 = c[i][jn][rh * 2 + 0] + bb.x;
                float v1 = c[i][jn][rh * 2 + 1] + bb.y;
                if (SPLIT_OUT) {
                    v0 = gelu_exact(v0);
                    v1 = gelu_exact(v1);
                    __half h0,l0,h1,l1;
                    split_f16(v0, h0, l0); split_f16(v1, h1, l1);
                    __half* ro = outS + (size_t)m * K2F + gc;
                    *reinterpret_cast<__half2*>(ro)        = __halves2half2(h0, h1);
                    *reinterpret_cast<__half2*>(ro + FEAT) = __halves2half2(l0, l1);
                } else {
                    float2 o{v0, v1};
                    *reinterpret_cast<float2*>(outF + (size_t)m * FEAT + gc) = o;
                }
            }
        }
    }
}

// ---------------------------------------------------------------------------
extern "C" void kernel_launch(void* const* d_in, const int* in_sizes, int n_in,
                              void* d_out, int out_size)
{
    const float* x  = (const float*)d_in[0];
    const float* W1 = (const float*)d_in[1];
    const float* b1 = (const float*)d_in[2];
    const float* W2 = (const float*)d_in[3];
    const float* b2 = (const float*)d_in[4];
    float* out = (float*)d_out;

    __half *a1, *h2, *w1t, *w2t;
    cudaGetSymbolAddress((void**)&a1,  g_a1);
    cudaGetSymbolAddress((void**)&h2,  g_h2);
    cudaGetSymbolAddress((void**)&w1t, g_w1t);
    cudaGetSymbolAddress((void**)&w2t, g_w2t);

    cudaFuncSetAttribute(hmma_gemm<K1F, true>,
                         cudaFuncAttributeMaxDynamicSharedMemorySize, SMEM_BYTES);
    cudaFuncSetAttribute(hmma_gemm<K2F, false>,
                         cudaFuncAttributeMaxDynamicSharedMemorySize, SMEM_BYTES);

    prep_w<<<dim3(FEAT / 32, DIN / 32),  256>>>(W1, w1t, DIN,  FEAT);
    prep_w<<<dim3(FEAT / 32, FEAT / 32), 256>>>(W2, w2t, FEAT, FEAT);
    feats_kernel<<<NROWS / 256, 256>>>(x, a1);

    dim3 grid(FEAT / 128, B_ROWS / 128);   // (4, 32) = 128 CTAs
    hmma_gemm<K1F, true ><<<grid, GT, SMEM_BYTES>>>(a1, w1t, b1, nullptr, h2);
    hmma_gemm<K2F, false><<<grid, GT, SMEM_BYTES>>>(h2, w2t, b2, out, nullptr);
}

// round 12
// speedup vs baseline: 1.5260x; 1.2381x over previous
#include <cuda_runtime.h>
#include <cuda_fp16.h>
#include <math.h>
#include <stdint.h>

#define B_ROWS   4096
#define T_LEN    256
#define NROWS    (B_ROWS * 64)
#define NFFT     24
#define FBINS    12
#define DIN      256
#define FEAT     512

// ---------------- scratch (__device__ globals; no allocs) ----------------
__device__ __half g_a1[B_ROWS * DIN];     // feats, fp16          2 MB
__device__ __half g_h2[B_ROWS * FEAT];    // hidden, fp16         4 MB
__device__ __half g_w1t[FEAT * DIN];      // W1^T fp16
__device__ __half g_w2t[FEAT * FEAT];     // W2^T fp16

// ---------------- helpers ----------------
__device__ __forceinline__ uint32_t smem_u32(const void* p) {
    uint32_t a;
    asm("{ .reg .u64 t; cvta.to.shared.u64 t, %1; cvt.u32.u64 %0, t; }"
        : "=r"(a) : "l"(p));
    return a;
}
__device__ __forceinline__ void cp16(uint32_t dst, const void* src) {
    asm volatile("cp.async.cg.shared.global [%0], [%1], 16;"
                 :: "r"(dst), "l"(src));
}
__device__ __forceinline__ void cp_commit() {
    asm volatile("cp.async.commit_group;");
}
template <int N>
__device__ __forceinline__ void cp_wait() {
    asm volatile("cp.async.wait_group %0;" :: "n"(N));
}
#define LDSM4(r, addr)                                                        \
    asm volatile("ldmatrix.sync.aligned.m8n8.x4.shared.b16 {%0,%1,%2,%3}, [%4];" \
                 : "=r"((r)[0]), "=r"((r)[1]), "=r"((r)[2]), "=r"((r)[3])     \
                 : "r"(addr))
#define MMA16816(d, a, b0, b1)                                                \
    asm volatile(                                                             \
        "mma.sync.aligned.m16n8k16.row.col.f32.f16.f16.f32 "                  \
        "{%0,%1,%2,%3}, {%4,%5,%6,%7}, {%8,%9}, {%0,%1,%2,%3};"               \
        : "+f"((d)[0]), "+f"((d)[1]), "+f"((d)[2]), "+f"((d)[3])              \
        : "r"((a)[0]), "r"((a)[1]), "r"((a)[2]), "r"((a)[3]),                 \
          "r"(b0), "r"(b1))

// packed fp32x2 helpers
__device__ __forceinline__ unsigned long long pack2(float lo, float hi) {
    unsigned long long r;
    asm("mov.b64 %0, {%1, %2};" : "=l"(r) : "f"(lo), "f"(hi));
    return r;
}
__device__ __forceinline__ void fma2(unsigned long long& d,
                                     unsigned long long a, unsigned long long b) {
    asm("fma.rn.f32x2 %0, %1, %2, %0;" : "+l"(d) : "l"(a), "l"(b));
}
__device__ __forceinline__ float2 unpack2(unsigned long long v) {
    float2 r;
    asm("mov.b64 {%0, %1}, %2;" : "=f"(r.x), "=f"(r.y) : "l"(v));
    return r;
}
__device__ __forceinline__ float gelu_exact(float v) {
    return 0.5f * v * (1.0f + erff(v * 0.70710678118654752f));
}

// ---------------------------------------------------------------------------
// Kernel 1: spectral features -> A [4096 x 256] fp16
// ---------------------------------------------------------------------------
__global__ __launch_bounds__(256) void feats_kernel(
    const float* __restrict__ x, __half* __restrict__ a1)
{
    __shared__ float2 s_tw[NFFT];
    int t = threadIdx.x;
    if (t < NFFT) {
        float s, c;
        sincospif((float)t / 12.0f, &s, &c);
        s_tw[t] = make_float2(c, -s);
    }
    __syncthreads();

    int row = blockIdx.x * 256 + t;

    unsigned long long tw[NFFT];
#pragma unroll
    for (int m = 0; m < NFFT; m++) { float2 v = s_tw[m]; tw[m] = pack2(v.x, v.y); }

    const float4* xp = reinterpret_cast<const float4*>(x + (size_t)row * T_LEN);
    float xs[NFFT];
#pragma unroll
    for (int i = 0; i < 6; i++) {
        float4 v = xp[i];
        xs[4*i + 0] = v.x; xs[4*i + 1] = v.y;
        xs[4*i + 2] = v.z; xs[4*i + 3] = v.w;
    }

    unsigned long long acc[FBINS];
#pragma unroll
    for (int k = 0; k < FBINS; k++) acc[k] = pack2(0.f, 0.f);
#pragma unroll
    for (int n = 0; n < NFFT; n++) {
        unsigned long long xv = pack2(xs[n], xs[n]);
#pragma unroll
        for (int k = 1; k <= FBINS; k++) {
            const int m = (k * n) % NFFT;
            fma2(acc[k-1], xv, tw[m]);
        }
    }

    float re[FBINS], im[FBINS], mag2[FBINS];
#pragma unroll
    for (int k = 0; k < FBINS; k++) {
        float2 p = unpack2(acc[k]);
        re[k] = p.x; im[k] = p.y;
        mag2[k] = p.x*p.x + p.y*p.y;
    }

    int i1 = 0; float m1 = mag2[0];
#pragma unroll
    for (int k = 1; k < FBINS; k++) if (mag2[k] > m1) { m1 = mag2[k]; i1 = k; }
    int i2 = (i1 == 0) ? 1 : 0; float m2 = mag2[i2];
#pragma unroll
    for (int k = 0; k < FBINS; k++)
        if (k != i1 && mag2[k] > m2) { m2 = mag2[k]; i2 = k; }

    float r1 = 0.f, q1 = 0.f, r2 = 0.f, q2 = 0.f;
#pragma unroll
    for (int k = 0; k < FBINS; k++) {
        if (k == i1) { r1 = re[k]; q1 = im[k]; }
        if (k == i2) { r2 = re[k]; q2 = im[k]; }
    }

    float o0 = sqrtf(m1);
    float o1 = sqrtf(m2);
    float o2 = atan2f(q1, r1);
    float o3 = atan2f(q2, r2);

    int b = row >> 6, c = row & 63;
    __half* base = a1 + (size_t)b * DIN + c * 4;
    reinterpret_cast<__half2*>(base)[0] =
        __halves2half2(__float2half_rn(o0), __float2half_rn(o1));
    reinterpret_cast<__half2*>(base)[1] =
        __halves2half2(__float2half_rn(o2), __float2half_rn(o3));
}

// ---------------------------------------------------------------------------
// W prep: W[K][N] fp32 -> Wt[N][K] fp16
// ---------------------------------------------------------------------------
__global__ __launch_bounds__(256) void prep_w(
    const float* __restrict__ W, __half* __restrict__ Tp, int K, int N)
{
    __shared__ float sm[32][33];
    int k0 = blockIdx.y * 32, n0 = blockIdx.x * 32;
    int tx = threadIdx.x & 31, ty = threadIdx.x >> 5;
#pragma unroll
    for (int i = ty; i < 32; i += 8)
        sm[i][tx] = W[(size_t)(k0 + i) * N + n0 + tx];
    __syncthreads();
#pragma unroll
    for (int r = ty; r < 32; r += 8)
        Tp[(size_t)(n0 + r) * K + k0 + tx] = __float2half_rn(sm[tx][r]);
}

// ---------------------------------------------------------------------------
// fp16 HMMA GEMM: CTA 128x128, 512 threads, 16 warps of 32x32,
// KC=64 (4 k16 phases/stage), 4-stage cp.async ring, frag double-buffering.
// Grid (4, 32) = 128 CTAs, 1 CTA/SM.
// ---------------------------------------------------------------------------
#define GT      512
#define KPAD    72
#define A_ELS   (128 * KPAD)
#define STGB    (2 * A_ELS * 2)
#define B_OFF   (A_ELS * 2)
#define NSTAGE  4
#define SMEM_BYTES (NSTAGE * STGB)        // 147456

template <int KTOT, bool SPLIT_OUT>
__global__ __launch_bounds__(GT, 1) void hmma_gemm(
    const __half* __restrict__ A, const __half* __restrict__ Bt,
    const float* __restrict__ bias,
    float* __restrict__ outF, __half* __restrict__ outS)
{
    extern __shared__ __half sm[];

    const int tid  = threadIdx.x;
    const int lane = tid & 31;
    const int wid  = tid >> 5;
    const int brow = blockIdx.y * 128;
    const int bcol = blockIdx.x * 128;
    const int m0 = (wid & 3) * 32;
    const int n0 = (wid >> 2) * 32;

    const __half* gAp[2];
    const __half* gBp[2];
    uint32_t sAo[2], sBo[2];
#pragma unroll
    for (int i = 0; i < 2; i++) {
        int u = i * GT + tid;
        int r = u >> 3, ch = u & 7;
        gAp[i] = A  + (size_t)(brow + r) * KTOT + ch * 8;
        gBp[i] = Bt + (size_t)(bcol + r) * KTOT + ch * 8;
        sAo[i] = smem_u32(sm) + (uint32_t)(r * KPAD * 2 + ch * 16);
        sBo[i] = sAo[i] + B_OFF;
    }

    auto copy_tile = [&](int kt, int slot) {
        const uint32_t so = slot * STGB;
        const int ko = kt * 64;
#pragma unroll
        for (int i = 0; i < 2; i++) cp16(sAo[i] + so, gAp[i] + ko);
#pragma unroll
        for (int i = 0; i < 2; i++) cp16(sBo[i] + so, gBp[i] + ko);
    };

    constexpr int NT = KTOT / 64;

#pragma unroll
    for (int p = 0; p < NSTAGE - 1; p++) {
        if (p < NT) copy_tile(p, p);
        cp_commit();
    }

    float c[2][4][4];
#pragma unroll
    for (int i = 0; i < 2; i++)
#pragma unroll
        for (int j = 0; j < 4; j++)
#pragma unroll
            for (int q = 0; q < 4; q++) c[i][j][q] = 0.0f;

    const int a_row = lane & 15;
    const int a_kh  = (lane >> 4) * 8;
    const int b_row = (lane & 7) + ((lane >> 4) << 3);
    const int b_kh  = ((lane >> 3) & 1) << 3;

    uint32_t aAddr[2], bAddr[2];
#pragma unroll
    for (int i = 0; i < 2; i++)
        aAddr[i] = smem_u32(&sm[(m0 + i * 16 + a_row) * KPAD + a_kh]);
#pragma unroll
    for (int j = 0; j < 2; j++)
        bAddr[j] = smem_u32(sm) + B_OFF +
                   (uint32_t)(((n0 + j * 16 + b_row) * KPAD + b_kh) * 2);

    uint32_t aF[2][2][4], bF[2][2][4];

    cp_wait<NSTAGE - 2>();
    __syncthreads();
#pragma unroll
    for (int i = 0; i < 2; i++) LDSM4(aF[0][i], aAddr[i]);
#pragma unroll
    for (int j = 0; j < 2; j++) LDSM4(bF[0][j], bAddr[j]);

    for (int kt = 0; kt < NT; kt++) {
        const uint32_t so  = (kt % NSTAGE) * STGB;
        const uint32_t so1 = ((kt + 1) % NSTAGE) * STGB;

#pragma unroll
        for (int ks = 0; ks < 4; ks++) {
            const int cb = ks & 1, nb = cb ^ 1;
            if (ks < 3) {
                const uint32_t po = so + (ks + 1) * 32;
#pragma unroll
                for (int i = 0; i < 2; i++) LDSM4(aF[nb][i], aAddr[i] + po);
#pragma unroll
                for (int j = 0; j < 2; j++) LDSM4(bF[nb][j], bAddr[j] + po);
            }
            if (ks == 1) {
                const int nk = kt + NSTAGE - 1;
                if (nk < NT) copy_tile(nk, nk % NSTAGE);
                cp_commit();
            }
            if (ks == 3) {
                cp_wait<NSTAGE - 2>();
                __syncthreads();
            }
#pragma unroll
            for (int i = 0; i < 2; i++)
#pragma unroll
                for (int jn = 0; jn < 4; jn++) {
                    const int j = jn >> 1;
                    if (jn & 1) MMA16816(c[i][jn], aF[cb][i], bF[cb][j][2], bF[cb][j][3]);
                    else        MMA16816(c[i][jn], aF[cb][i], bF[cb][j][0], bF[cb][j][1]);
                }
        }

        if (kt + 1 < NT) {
#pragma unroll
            for (int i = 0; i < 2; i++) LDSM4(aF[0][i], aAddr[i] + so1);
#pragma unroll
            for (int j = 0; j < 2; j++) LDSM4(bF[0][j], bAddr[j] + so1);
        }
    }

    // ---- epilogue ----
#pragma unroll
    for (int i = 0; i < 2; i++) {
        const int gm = brow + m0 + i * 16 + (lane >> 2);
#pragma unroll
        for (int jn = 0; jn < 4; jn++) {
            const int gc = bcol + n0 + jn * 8 + ((lane & 3) << 1);
            float2 bb = *reinterpret_cast<const float2*>(bias + gc);
#pragma unroll
            for (int rh = 0; rh < 2; rh++) {
                const int m = gm + rh * 8;
                float v0 = c[i][jn][rh * 2 + 0] + bb.x;
                float v1 = c[i][jn][rh * 2 + 1] + bb.y;
                if (SPLIT_OUT) {
                    v0 = gelu_exact(v0);
                    v1 = gelu_exact(v1);
                    *reinterpret_cast<__half2*>(outS + (size_t)m * FEAT + gc) =
                        __halves2half2(__float2half_rn(v0), __float2half_rn(v1));
                } else {
                    float2 o{v0, v1};
                    *reinterpret_cast<float2*>(outF + (size_t)m * FEAT + gc) = o;
                }
            }
        }
    }
}

// ---------------------------------------------------------------------------
extern "C" void kernel_launch(void* const* d_in, const int* in_sizes, int n_in,
                              void* d_out, int out_size)
{
    const float* x  = (const float*)d_in[0];
    const float* W1 = (const float*)d_in[1];
    const float* b1 = (const float*)d_in[2];
    const float* W2 = (const float*)d_in[3];
    const float* b2 = (const float*)d_in[4];
    float* out = (float*)d_out;

    __half *a1, *h2, *w1t, *w2t;
    cudaGetSymbolAddress((void**)&a1,  g_a1);
    cudaGetSymbolAddress((void**)&h2,  g_h2);
    cudaGetSymbolAddress((void**)&w1t, g_w1t);
    cudaGetSymbolAddress((void**)&w2t, g_w2t);

    cudaFuncSetAttribute(hmma_gemm<DIN, true>,
                         cudaFuncAttributeMaxDynamicSharedMemorySize, SMEM_BYTES);
    cudaFuncSetAttribute(hmma_gemm<FEAT, false>,
                         cudaFuncAttributeMaxDynamicSharedMemorySize, SMEM_BYTES);

    prep_w<<<dim3(FEAT / 32, DIN / 32),  256>>>(W1, w1t, DIN,  FEAT);
    prep_w<<<dim3(FEAT / 32, FEAT / 32), 256>>>(W2, w2t, FEAT, FEAT);
    feats_kernel<<<NROWS / 256, 256>>>(x, a1);

    dim3 grid(FEAT / 128, B_ROWS / 128);   // (4, 32) = 128 CTAs
    hmma_gemm<DIN,  true ><<<grid, GT, SMEM_BYTES>>>(a1, w1t, b1, nullptr, h2);
    hmma_gemm<FEAT, false><<<grid, GT, SMEM_BYTES>>>(h2, w2t, b2, out, nullptr);
}

// round 13
// speedup vs baseline: 1.6853x; 1.1044x over previous
#include <cuda_runtime.h>
#include <cuda_fp16.h>
#include <math.h>
#include <stdint.h>

#define B_ROWS   4096
#define T_LEN    256
#define NROWS    (B_ROWS * 64)
#define NFFT     24
#define FBINS    12
#define DIN      256
#define FEAT     512

// ---------------- scratch (__device__ globals; no allocs) ----------------
__device__ __half g_a1[B_ROWS * DIN];     // feats, fp16          2 MB
__device__ __half g_h2[B_ROWS * FEAT];    // hidden, fp16         4 MB
__device__ __half g_w1t[FEAT * DIN];      // W1^T fp16
__device__ __half g_w2t[FEAT * FEAT];     // W2^T fp16

// ---------------- helpers ----------------
__device__ __forceinline__ uint32_t smem_u32(const void* p) {
    uint32_t a;
    asm("{ .reg .u64 t; cvta.to.shared.u64 t, %1; cvt.u32.u64 %0, t; }"
        : "=r"(a) : "l"(p));
    return a;
}
__device__ __forceinline__ void cp16(uint32_t dst, const void* src) {
    asm volatile("cp.async.cg.shared.global [%0], [%1], 16;"
                 :: "r"(dst), "l"(src));
}
__device__ __forceinline__ void cp_commit() {
    asm volatile("cp.async.commit_group;");
}
template <int N>
__device__ __forceinline__ void cp_wait() {
    asm volatile("cp.async.wait_group %0;" :: "n"(N));
}
#define LDSM4(r, addr)                                                        \
    asm volatile("ldmatrix.sync.aligned.m8n8.x4.shared.b16 {%0,%1,%2,%3}, [%4];" \
                 : "=r"((r)[0]), "=r"((r)[1]), "=r"((r)[2]), "=r"((r)[3])     \
                 : "r"(addr))
#define MMA16816(d, a, b0, b1)                                                \
    asm volatile(                                                             \
        "mma.sync.aligned.m16n8k16.row.col.f32.f16.f16.f32 "                  \
        "{%0,%1,%2,%3}, {%4,%5,%6,%7}, {%8,%9}, {%0,%1,%2,%3};"               \
        : "+f"((d)[0]), "+f"((d)[1]), "+f"((d)[2]), "+f"((d)[3])              \
        : "r"((a)[0]), "r"((a)[1]), "r"((a)[2]), "r"((a)[3]),                 \
          "r"(b0), "r"(b1))

// packed fp32x2 helpers
__device__ __forceinline__ unsigned long long pack2(float lo, float hi) {
    unsigned long long r;
    asm("mov.b64 %0, {%1, %2};" : "=l"(r) : "f"(lo), "f"(hi));
    return r;
}
__device__ __forceinline__ void fma2(unsigned long long& d,
                                     unsigned long long a, unsigned long long b) {
    asm("fma.rn.f32x2 %0, %1, %2, %0;" : "+l"(d) : "l"(a), "l"(b));
}
__device__ __forceinline__ float2 unpack2(unsigned long long v) {
    float2 r;
    asm("mov.b64 {%0, %1}, %2;" : "=f"(r.x), "=f"(r.y) : "l"(v));
    return r;
}
__device__ __forceinline__ float gelu_exact(float v) {
    return 0.5f * v * (1.0f + erff(v * 0.70710678118654752f));
}

// ---------------------------------------------------------------------------
// Kernel 1: spectral features -> A [4096 x 256] fp16
// Cooperative smem-staged loads: block reads its 256 rows' first 96 B
// coalesced (~6 lines per warp-instruction instead of 32).
// ---------------------------------------------------------------------------
#define XPAD 28    // floats per smem row (112 B): conflict-free for LDS.128

__global__ __launch_bounds__(256) void feats_kernel(
    const float* __restrict__ x, __half* __restrict__ a1)
{
    __shared__ float sX[256 * XPAD];      // 28.7 KB
    __shared__ float2 s_tw[NFFT];
    const int t = threadIdx.x;
    if (t < NFFT) {
        float s, c;
        sincospif((float)t / 12.0f, &s, &c);
        s_tw[t] = make_float2(c, -s);
    }

    // cooperative load: 256 rows x 6 float4-chunks = 1536 chunks
    const float* gx = x + (size_t)blockIdx.x * 256 * T_LEN;
#pragma unroll
    for (int k = 0; k < 6; k++) {
        const int c   = t + k * 256;
        const int row = c / 6;
        const int off = c - row * 6;
        float4 v = *reinterpret_cast<const float4*>(
            gx + (size_t)row * T_LEN + off * 4);
        *reinterpret_cast<float4*>(&sX[row * XPAD + off * 4]) = v;
    }
    __syncthreads();

    unsigned long long tw[NFFT];
#pragma unroll
    for (int m = 0; m < NFFT; m++) { float2 v = s_tw[m]; tw[m] = pack2(v.x, v.y); }

    float xs[NFFT];
#pragma unroll
    for (int i = 0; i < 6; i++) {
        float4 v = *reinterpret_cast<const float4*>(&sX[t * XPAD + i * 4]);
        xs[4*i + 0] = v.x; xs[4*i + 1] = v.y;
        xs[4*i + 2] = v.z; xs[4*i + 3] = v.w;
    }

    unsigned long long acc[FBINS];
#pragma unroll
    for (int k = 0; k < FBINS; k++) acc[k] = pack2(0.f, 0.f);
#pragma unroll
    for (int n = 0; n < NFFT; n++) {
        unsigned long long xv = pack2(xs[n], xs[n]);
#pragma unroll
        for (int k = 1; k <= FBINS; k++) {
            const int m = (k * n) % NFFT;
            fma2(acc[k-1], xv, tw[m]);
        }
    }

    float re[FBINS], im[FBINS], mag2[FBINS];
#pragma unroll
    for (int k = 0; k < FBINS; k++) {
        float2 p = unpack2(acc[k]);
        re[k] = p.x; im[k] = p.y;
        mag2[k] = p.x*p.x + p.y*p.y;
    }

    int i1 = 0; float m1 = mag2[0];
#pragma unroll
    for (int k = 1; k < FBINS; k++) if (mag2[k] > m1) { m1 = mag2[k]; i1 = k; }
    int i2 = (i1 == 0) ? 1 : 0; float m2 = mag2[i2];
#pragma unroll
    for (int k = 0; k < FBINS; k++)
        if (k != i1 && mag2[k] > m2) { m2 = mag2[k]; i2 = k; }

    float r1 = 0.f, q1 = 0.f, r2 = 0.f, q2 = 0.f;
#pragma unroll
    for (int k = 0; k < FBINS; k++) {
        if (k == i1) { r1 = re[k]; q1 = im[k]; }
        if (k == i2) { r2 = re[k]; q2 = im[k]; }
    }

    float o0 = sqrtf(m1);
    float o1 = sqrtf(m2);
    float o2 = atan2f(q1, r1);
    float o3 = atan2f(q2, r2);

    const int row = blockIdx.x * 256 + t;
    const int b = row >> 6, c = row & 63;
    __half* base = a1 + (size_t)b * DIN + c * 4;
    reinterpret_cast<__half2*>(base)[0] =
        __halves2half2(__float2half_rn(o0), __float2half_rn(o1));
    reinterpret_cast<__half2*>(base)[1] =
        __halves2half2(__float2half_rn(o2), __float2half_rn(o3));
}

// ---------------------------------------------------------------------------
// W prep: W[K][N] fp32 -> Wt[N][K] fp16
// ---------------------------------------------------------------------------
__global__ __launch_bounds__(256) void prep_w(
    const float* __restrict__ W, __half* __restrict__ Tp, int K, int N)
{
    __shared__ float sm[32][33];
    int k0 = blockIdx.y * 32, n0 = blockIdx.x * 32;
    int tx = threadIdx.x & 31, ty = threadIdx.x >> 5;
#pragma unroll
    for (int i = ty; i < 32; i += 8)
        sm[i][tx] = W[(size_t)(k0 + i) * N + n0 + tx];
    __syncthreads();
#pragma unroll
    for (int r = ty; r < 32; r += 8)
        Tp[(size_t)(n0 + r) * K + k0 + tx] = __float2half_rn(sm[tx][r]);
}

// ---------------------------------------------------------------------------
// fp16 HMMA GEMM: CTA 128x128, 512 threads, 16 warps of 32x32,
// KC=64 (4 k16 phases/stage), 4-stage cp.async ring, frag double-buffering.
// Grid (4, 32) = 128 CTAs, 1 CTA/SM.
// ---------------------------------------------------------------------------
#define GT      512
#define KPAD    72
#define A_ELS   (128 * KPAD)
#define STGB    (2 * A_ELS * 2)
#define B_OFF   (A_ELS * 2)
#define NSTAGE  4
#define SMEM_BYTES (NSTAGE * STGB)        // 147456

template <int KTOT, bool SPLIT_OUT>
__global__ __launch_bounds__(GT, 1) void hmma_gemm(
    const __half* __restrict__ A, const __half* __restrict__ Bt,
    const float* __restrict__ bias,
    float* __restrict__ outF, __half* __restrict__ outS)
{
    extern __shared__ __half sm[];

    const int tid  = threadIdx.x;
    const int lane = tid & 31;
    const int wid  = tid >> 5;
    const int brow = blockIdx.y * 128;
    const int bcol = blockIdx.x * 128;
    const int m0 = (wid & 3) * 32;
    const int n0 = (wid >> 2) * 32;

    const __half* gAp[2];
    const __half* gBp[2];
    uint32_t sAo[2], sBo[2];
#pragma unroll
    for (int i = 0; i < 2; i++) {
        int u = i * GT + tid;
        int r = u >> 3, ch = u & 7;
        gAp[i] = A  + (size_t)(brow + r) * KTOT + ch * 8;
        gBp[i] = Bt + (size_t)(bcol + r) * KTOT + ch * 8;
        sAo[i] = smem_u32(sm) + (uint32_t)(r * KPAD * 2 + ch * 16);
        sBo[i] = sAo[i] + B_OFF;
    }

    auto copy_tile = [&](int kt, int slot) {
        const uint32_t so = slot * STGB;
        const int ko = kt * 64;
#pragma unroll
        for (int i = 0; i < 2; i++) cp16(sAo[i] + so, gAp[i] + ko);
#pragma unroll
        for (int i = 0; i < 2; i++) cp16(sBo[i] + so, gBp[i] + ko);
    };

    constexpr int NT = KTOT / 64;

#pragma unroll
    for (int p = 0; p < NSTAGE - 1; p++) {
        if (p < NT) copy_tile(p, p);
        cp_commit();
    }

    float c[2][4][4];
#pragma unroll
    for (int i = 0; i < 2; i++)
#pragma unroll
        for (int j = 0; j < 4; j++)
#pragma unroll
            for (int q = 0; q < 4; q++) c[i][j][q] = 0.0f;

    const int a_row = lane & 15;
    const int a_kh  = (lane >> 4) * 8;
    const int b_row = (lane & 7) + ((lane >> 4) << 3);
    const int b_kh  = ((lane >> 3) & 1) << 3;

    uint32_t aAddr[2], bAddr[2];
#pragma unroll
    for (int i = 0; i < 2; i++)
        aAddr[i] = smem_u32(&sm[(m0 + i * 16 + a_row) * KPAD + a_kh]);
#pragma unroll
    for (int j = 0; j < 2; j++)
        bAddr[j] = smem_u32(sm) + B_OFF +
                   (uint32_t)(((n0 + j * 16 + b_row) * KPAD + b_kh) * 2);

    uint32_t aF[2][2][4], bF[2][2][4];

    cp_wait<NSTAGE - 2>();
    __syncthreads();
#pragma unroll
    for (int i = 0; i < 2; i++) LDSM4(aF[0][i], aAddr[i]);
#pragma unroll
    for (int j = 0; j < 2; j++) LDSM4(bF[0][j], bAddr[j]);

    for (int kt = 0; kt < NT; kt++) {
        const uint32_t so  = (kt % NSTAGE) * STGB;
        const uint32_t so1 = ((kt + 1) % NSTAGE) * STGB;

#pragma unroll
        for (int ks = 0; ks < 4; ks++) {
            const int cb = ks & 1, nb = cb ^ 1;
            if (ks < 3) {
                const uint32_t po = so + (ks + 1) * 32;
#pragma unroll
                for (int i = 0; i < 2; i++) LDSM4(aF[nb][i], aAddr[i] + po);
#pragma unroll
                for (int j = 0; j < 2; j++) LDSM4(bF[nb][j], bAddr[j] + po);
            }
            if (ks == 1) {
                const int nk = kt + NSTAGE - 1;
                if (nk < NT) copy_tile(nk, nk % NSTAGE);
                cp_commit();
            }
            if (ks == 3) {
                cp_wait<NSTAGE - 2>();
                __syncthreads();
            }
#pragma unroll
            for (int i = 0; i < 2; i++)
#pragma unroll
                for (int jn = 0; jn < 4; jn++) {
                    const int j = jn >> 1;
                    if (jn & 1) MMA16816(c[i][jn], aF[cb][i], bF[cb][j][2], bF[cb][j][3]);
                    else        MMA16816(c[i][jn], aF[cb][i], bF[cb][j][0], bF[cb][j][1]);
                }
        }

        if (kt + 1 < NT) {
#pragma unroll
            for (int i = 0; i < 2; i++) LDSM4(aF[0][i], aAddr[i] + so1);
#pragma unroll
            for (int j = 0; j < 2; j++) LDSM4(bF[0][j], bAddr[j] + so1);
        }
    }

    // ---- epilogue ----
#pragma unroll
    for (int i = 0; i < 2; i++) {
        const int gm = brow + m0 + i * 16 + (lane >> 2);
#pragma unroll
        for (int jn = 0; jn < 4; jn++) {
            const int gc = bcol + n0 + jn * 8 + ((lane & 3) << 1);
            float2 bb = *reinterpret_cast<const float2*>(bias + gc);
#pragma unroll
            for (int rh = 0; rh < 2; rh++) {
                const int m = gm + rh * 8;
                float v0 = c[i][jn][rh * 2 + 0] + bb.x;
                float v1 = c[i][jn][rh * 2 + 1] + bb.y;
                if (SPLIT_OUT) {
                    v0 = gelu_exact(v0);
                    v1 = gelu_exact(v1);
                    *reinterpret_cast<__half2*>(outS + (size_t)m * FEAT + gc) =
                        __halves2half2(__float2half_rn(v0), __float2half_rn(v1));
                } else {
                    float2 o{v0, v1};
                    *reinterpret_cast<float2*>(outF + (size_t)m * FEAT + gc) = o;
                }
            }
        }
    }
}

// ---------------------------------------------------------------------------
extern "C" void kernel_launch(void* const* d_in, const int* in_sizes, int n_in,
                              void* d_out, int out_size)
{
    const float* x  = (const float*)d_in[0];
    const float* W1 = (const float*)d_in[1];
    const float* b1 = (const float*)d_in[2];
    const float* W2 = (const float*)d_in[3];
    const float* b2 = (const float*)d_in[4];
    float* out = (float*)d_out;

    __half *a1, *h2, *w1t, *w2t;
    cudaGetSymbolAddress((void**)&a1,  g_a1);
    cudaGetSymbolAddress((void**)&h2,  g_h2);
    cudaGetSymbolAddress((void**)&w1t, g_w1t);
    cudaGetSymbolAddress((void**)&w2t, g_w2t);

    cudaFuncSetAttribute(hmma_gemm<DIN, true>,
                         cudaFuncAttributeMaxDynamicSharedMemorySize, SMEM_BYTES);
    cudaFuncSetAttribute(hmma_gemm<FEAT, false>,
                         cudaFuncAttributeMaxDynamicSharedMemorySize, SMEM_BYTES);

    prep_w<<<dim3(FEAT / 32, DIN / 32),  256>>>(W1, w1t, DIN,  FEAT);
    prep_w<<<dim3(FEAT / 32, FEAT / 32), 256>>>(W2, w2t, FEAT, FEAT);
    feats_kernel<<<NROWS / 256, 256>>>(x, a1);

    dim3 grid(FEAT / 128, B_ROWS / 128);   // (4, 32) = 128 CTAs
    hmma_gemm<DIN,  true ><<<grid, GT, SMEM_BYTES>>>(a1, w1t, b1, nullptr, h2);
    hmma_gemm<FEAT, false><<<grid, GT, SMEM_BYTES>>>(h2, w2t, b2, out, nullptr);
}

// round 14
// speedup vs baseline: 1.7819x; 1.0573x over previous
#include <cuda_runtime.h>
#include <cuda_fp16.h>
#include <math.h>
#include <stdint.h>

#define B_ROWS   4096
#define T_LEN    256
#define NROWS    (B_ROWS * 64)
#define NFFT     24
#define FBINS    12
#define DIN      256
#define FEAT     512

// ---------------- scratch (__device__ globals; no allocs) ----------------
__device__ __half g_a1[B_ROWS * DIN];     // feats, fp16          2 MB
__device__ __half g_h2[B_ROWS * FEAT];    // hidden, fp16         4 MB
__device__ __half g_w1t[FEAT * DIN];      // W1^T fp16
__device__ __half g_w2t[FEAT * FEAT];     // W2^T fp16

// ---------------- helpers ----------------
__device__ __forceinline__ uint32_t smem_u32(const void* p) {
    uint32_t a;
    asm("{ .reg .u64 t; cvta.to.shared.u64 t, %1; cvt.u32.u64 %0, t; }"
        : "=r"(a) : "l"(p));
    return a;
}
__device__ __forceinline__ void cp16(uint32_t dst, const void* src) {
    asm volatile("cp.async.cg.shared.global [%0], [%1], 16;"
                 :: "r"(dst), "l"(src));
}
__device__ __forceinline__ void cp_commit() {
    asm volatile("cp.async.commit_group;");
}
template <int N>
__device__ __forceinline__ void cp_wait() {
    asm volatile("cp.async.wait_group %0;" :: "n"(N));
}
#define LDSM4(r, addr)                                                        \
    asm volatile("ldmatrix.sync.aligned.m8n8.x4.shared.b16 {%0,%1,%2,%3}, [%4];" \
                 : "=r"((r)[0]), "=r"((r)[1]), "=r"((r)[2]), "=r"((r)[3])     \
                 : "r"(addr))
#define MMA16816(d, a, b0, b1)                                                \
    asm volatile(                                                             \
        "mma.sync.aligned.m16n8k16.row.col.f32.f16.f16.f32 "                  \
        "{%0,%1,%2,%3}, {%4,%5,%6,%7}, {%8,%9}, {%0,%1,%2,%3};"               \
        : "+f"((d)[0]), "+f"((d)[1]), "+f"((d)[2]), "+f"((d)[3])              \
        : "r"((a)[0]), "r"((a)[1]), "r"((a)[2]), "r"((a)[3]),                 \
          "r"(b0), "r"(b1))

// packed fp32x2 helpers
__device__ __forceinline__ unsigned long long pack2(float lo, float hi) {
    unsigned long long r;
    asm("mov.b64 %0, {%1, %2};" : "=l"(r) : "f"(lo), "f"(hi));
    return r;
}
__device__ __forceinline__ void fma2(unsigned long long& d,
                                     unsigned long long a, unsigned long long b) {
    asm("fma.rn.f32x2 %0, %1, %2, %0;" : "+l"(d) : "l"(a), "l"(b));
}
__device__ __forceinline__ float2 unpack2(unsigned long long v) {
    float2 r;
    asm("mov.b64 {%0, %1}, %2;" : "=f"(r.x), "=f"(r.y) : "l"(v));
    return r;
}
__device__ __forceinline__ float gelu_exact(float v) {
    return 0.5f * v * (1.0f + erff(v * 0.70710678118654752f));
}

// ---------------------------------------------------------------------------
// Fused pre-pass: blocks [0,1024) = feats; [1024,1152) = prep W1;
//                 [1152,1408) = prep W2.
// ---------------------------------------------------------------------------
#define XPAD 28    // floats per smem row (112 B)

__device__ void feats_body(const float* __restrict__ x,
                           __half* __restrict__ a1, int bx)
{
    __shared__ float sX[256 * XPAD];      // 28.7 KB
    __shared__ float2 s_tw[NFFT];
    const int t = threadIdx.x;
    if (t < NFFT) {
        float s, c;
        sincospif((float)t / 12.0f, &s, &c);
        s_tw[t] = make_float2(c, -s);
    }

    const float* gx = x + (size_t)bx * 256 * T_LEN;
#pragma unroll
    for (int k = 0; k < 6; k++) {
        const int c   = t + k * 256;
        const int row = c / 6;
        const int off = c - row * 6;
        float4 v = *reinterpret_cast<const float4*>(
            gx + (size_t)row * T_LEN + off * 4);
        *reinterpret_cast<float4*>(&sX[row * XPAD + off * 4]) = v;
    }
    __syncthreads();

    unsigned long long tw[NFFT];
#pragma unroll
    for (int m = 0; m < NFFT; m++) { float2 v = s_tw[m]; tw[m] = pack2(v.x, v.y); }

    float xs[NFFT];
#pragma unroll
    for (int i = 0; i < 6; i++) {
        float4 v = *reinterpret_cast<const float4*>(&sX[t * XPAD + i * 4]);
        xs[4*i + 0] = v.x; xs[4*i + 1] = v.y;
        xs[4*i + 2] = v.z; xs[4*i + 3] = v.w;
    }

    unsigned long long acc[FBINS];
#pragma unroll
    for (int k = 0; k < FBINS; k++) acc[k] = pack2(0.f, 0.f);
#pragma unroll
    for (int n = 0; n < NFFT; n++) {
        unsigned long long xv = pack2(xs[n], xs[n]);
#pragma unroll
        for (int k = 1; k <= FBINS; k++) {
            const int m = (k * n) % NFFT;
            fma2(acc[k-1], xv, tw[m]);
        }
    }

    float re[FBINS], im[FBINS], mag2[FBINS];
#pragma unroll
    for (int k = 0; k < FBINS; k++) {
        float2 p = unpack2(acc[k]);
        re[k] = p.x; im[k] = p.y;
        mag2[k] = p.x*p.x + p.y*p.y;
    }

    int i1 = 0; float m1 = mag2[0];
#pragma unroll
    for (int k = 1; k < FBINS; k++) if (mag2[k] > m1) { m1 = mag2[k]; i1 = k; }
    int i2 = (i1 == 0) ? 1 : 0; float m2 = mag2[i2];
#pragma unroll
    for (int k = 0; k < FBINS; k++)
        if (k != i1 && mag2[k] > m2) { m2 = mag2[k]; i2 = k; }

    float r1 = 0.f, q1 = 0.f, r2 = 0.f, q2 = 0.f;
#pragma unroll
    for (int k = 0; k < FBINS; k++) {
        if (k == i1) { r1 = re[k]; q1 = im[k]; }
        if (k == i2) { r2 = re[k]; q2 = im[k]; }
    }

    float o0 = sqrtf(m1);
    float o1 = sqrtf(m2);
    float o2 = atan2f(q1, r1);
    float o3 = atan2f(q2, r2);

    const int row = bx * 256 + t;
    const int b = row >> 6, c = row & 63;
    __half* base = a1 + (size_t)b * DIN + c * 4;
    reinterpret_cast<__half2*>(base)[0] =
        __halves2half2(__float2half_rn(o0), __float2half_rn(o1));
    reinterpret_cast<__half2*>(base)[1] =
        __halves2half2(__float2half_rn(o2), __float2half_rn(o3));
}

__device__ void prep_body(const float* __restrict__ W, __half* __restrict__ Tp,
                          int K, int N, int n0, int k0)
{
    __shared__ float sm[32][33];
    int tx = threadIdx.x & 31, ty = threadIdx.x >> 5;
#pragma unroll
    for (int i = ty; i < 32; i += 8)
        sm[i][tx] = W[(size_t)(k0 + i) * N + n0 + tx];
    __syncthreads();
#pragma unroll
    for (int r = ty; r < 32; r += 8)
        Tp[(size_t)(n0 + r) * K + k0 + tx] = __float2half_rn(sm[tx][r]);
}

__global__ __launch_bounds__(256) void pre_kernel(
    const float* __restrict__ x, __half* __restrict__ a1,
    const float* __restrict__ W1, __half* __restrict__ w1t,
    const float* __restrict__ W2, __half* __restrict__ w2t)
{
    const int bx = blockIdx.x;
    if (bx < 1024) {
        feats_body(x, a1, bx);
    } else if (bx < 1024 + 128) {
        const int bid = bx - 1024;                 // W1: (N/32=16) x (K/32=8)
        prep_body(W1, w1t, DIN, FEAT, (bid & 15) * 32, (bid >> 4) * 32);
    } else {
        const int bid = bx - 1152;                 // W2: 16 x 16
        prep_body(W2, w2t, FEAT, FEAT, (bid & 15) * 32, (bid >> 4) * 32);
    }
}

// ---------------------------------------------------------------------------
// fp16 HMMA GEMM: CTA 64x128 (MxN), 256 threads, 8 warps of 32x32,
// KC=64 (4 k16 phases/stage), 3-stage cp.async ring, frag double-buffering.
// Grid (4, 64) = 256 CTAs, 2 CTAs/SM (fixed-latency overlap).
// ---------------------------------------------------------------------------
#define GT      256
#define KPAD    72
#define A_ROWS  64
#define B_ROWS_T 128
#define A_BYTES (A_ROWS * KPAD * 2)       // 9216
#define B_OFF   A_BYTES
#define STGB    (A_BYTES + B_ROWS_T * KPAD * 2)   // 27648
#define NSTAGE  3
#define SMEM_BYTES (NSTAGE * STGB)        // 82944

template <int KTOT, bool SPLIT_OUT>
__global__ __launch_bounds__(GT, 2) void hmma_gemm(
    const __half* __restrict__ A, const __half* __restrict__ Bt,
    const float* __restrict__ bias,
    float* __restrict__ outF, __half* __restrict__ outS)
{
    extern __shared__ __half sm[];

    const int tid  = threadIdx.x;
    const int lane = tid & 31;
    const int wid  = tid >> 5;
    const int brow = blockIdx.y * 64;
    const int bcol = blockIdx.x * 128;
    const int m0 = (wid & 1) * 32;        // 2 warps in m
    const int n0 = (wid >> 1) * 32;       // 4 warps in n

    // copy setup: A = 64 rows x 8 chunks = 512; B = 128 rows x 8 = 1024.
    const __half* gAp[2];
    const __half* gBp[4];
    uint32_t sAo[2], sBo[4];
#pragma unroll
    for (int i = 0; i < 2; i++) {
        int u = i * GT + tid;
        int r = u >> 3, ch = u & 7;
        gAp[i] = A + (size_t)(brow + r) * KTOT + ch * 8;
        sAo[i] = smem_u32(sm) + (uint32_t)(r * KPAD * 2 + ch * 16);
    }
#pragma unroll
    for (int i = 0; i < 4; i++) {
        int u = i * GT + tid;
        int r = u >> 3, ch = u & 7;
        gBp[i] = Bt + (size_t)(bcol + r) * KTOT + ch * 8;
        sBo[i] = smem_u32(sm) + B_OFF + (uint32_t)(r * KPAD * 2 + ch * 16);
    }

    auto copy_tile = [&](int kt, int slot) {
        const uint32_t so = slot * STGB;
        const int ko = kt * 64;
#pragma unroll
        for (int i = 0; i < 2; i++) cp16(sAo[i] + so, gAp[i] + ko);
#pragma unroll
        for (int i = 0; i < 4; i++) cp16(sBo[i] + so, gBp[i] + ko);
    };

    constexpr int NT = KTOT / 64;

#pragma unroll
    for (int p = 0; p < NSTAGE - 1; p++) {
        if (p < NT) copy_tile(p, p);
        cp_commit();
    }

    float c[2][4][4];
#pragma unroll
    for (int i = 0; i < 2; i++)
#pragma unroll
        for (int j = 0; j < 4; j++)
#pragma unroll
            for (int q = 0; q < 4; q++) c[i][j][q] = 0.0f;

    const int a_row = lane & 15;
    const int a_kh  = (lane >> 4) * 8;
    const int b_row = (lane & 7) + ((lane >> 4) << 3);
    const int b_kh  = ((lane >> 3) & 1) << 3;

    uint32_t aAddr[2], bAddr[2];
#pragma unroll
    for (int i = 0; i < 2; i++)
        aAddr[i] = smem_u32(&sm[(m0 + i * 16 + a_row) * KPAD + a_kh]);
#pragma unroll
    for (int j = 0; j < 2; j++)
        bAddr[j] = smem_u32(sm) + B_OFF +
                   (uint32_t)(((n0 + j * 16 + b_row) * KPAD + b_kh) * 2);

    uint32_t aF[2][2][4], bF[2][2][4];

    cp_wait<NSTAGE - 2>();
    __syncthreads();
#pragma unroll
    for (int i = 0; i < 2; i++) LDSM4(aF[0][i], aAddr[i]);
#pragma unroll
    for (int j = 0; j < 2; j++) LDSM4(bF[0][j], bAddr[j]);

    for (int kt = 0; kt < NT; kt++) {
        const uint32_t so  = (kt % NSTAGE) * STGB;
        const uint32_t so1 = ((kt + 1) % NSTAGE) * STGB;

#pragma unroll
        for (int ks = 0; ks < 4; ks++) {
            const int cb = ks & 1, nb = cb ^ 1;
            if (ks < 3) {
                const uint32_t po = so + (ks + 1) * 32;
#pragma unroll
                for (int i = 0; i < 2; i++) LDSM4(aF[nb][i], aAddr[i] + po);
#pragma unroll
                for (int j = 0; j < 2; j++) LDSM4(bF[nb][j], bAddr[j] + po);
            }
            if (ks == 1) {
                const int nk = kt + NSTAGE - 1;
                if (nk < NT) copy_tile(nk, nk % NSTAGE);
                cp_commit();
            }
            if (ks == 3) {
                cp_wait<NSTAGE - 2>();
                __syncthreads();
            }
#pragma unroll
            for (int i = 0; i < 2; i++)
#pragma unroll
                for (int jn = 0; jn < 4; jn++) {
                    const int j = jn >> 1;
                    if (jn & 1) MMA16816(c[i][jn], aF[cb][i], bF[cb][j][2], bF[cb][j][3]);
                    else        MMA16816(c[i][jn], aF[cb][i], bF[cb][j][0], bF[cb][j][1]);
                }
        }

        if (kt + 1 < NT) {
#pragma unroll
            for (int i = 0; i < 2; i++) LDSM4(aF[0][i], aAddr[i] + so1);
#pragma unroll
            for (int j = 0; j < 2; j++) LDSM4(bF[0][j], bAddr[j] + so1);
        }
    }

    // ---- epilogue ----
#pragma unroll
    for (int i = 0; i < 2; i++) {
        const int gm = brow + m0 + i * 16 + (lane >> 2);
#pragma unroll
        for (int jn = 0; jn < 4; jn++) {
            const int gc = bcol + n0 + jn * 8 + ((lane & 3) << 1);
            float2 bb = *reinterpret_cast<const float2*>(bias + gc);
#pragma unroll
            for (int rh = 0; rh < 2; rh++) {
                const int m = gm + rh * 8;
                float v0 = c[i][jn][rh * 2 + 0] + bb.x;
                float v1 = c[i][jn][rh * 2 + 1] + bb.y;
                if (SPLIT_OUT) {
                    v0 = gelu_exact(v0);
                    v1 = gelu_exact(v1);
                    *reinterpret_cast<__half2*>(outS + (size_t)m * FEAT + gc) =
                        __halves2half2(__float2half_rn(v0), __float2half_rn(v1));
                } else {
                    float2 o{v0, v1};
                    *reinterpret_cast<float2*>(outF + (size_t)m * FEAT + gc) = o;
                }
            }
        }
    }
}

// ---------------------------------------------------------------------------
extern "C" void kernel_launch(void* const* d_in, const int* in_sizes, int n_in,
                              void* d_out, int out_size)
{
    const float* x  = (const float*)d_in[0];
    const float* W1 = (const float*)d_in[1];
    const float* b1 = (const float*)d_in[2];
    const float* W2 = (const float*)d_in[3];
    const float* b2 = (const float*)d_in[4];
    float* out = (float*)d_out;

    __half *a1, *h2, *w1t, *w2t;
    cudaGetSymbolAddress((void**)&a1,  g_a1);
    cudaGetSymbolAddress((void**)&h2,  g_h2);
    cudaGetSymbolAddress((void**)&w1t, g_w1t);
    cudaGetSymbolAddress((void**)&w2t, g_w2t);

    cudaFuncSetAttribute(hmma_gemm<DIN, true>,
                         cudaFuncAttributeMaxDynamicSharedMemorySize, SMEM_BYTES);
    cudaFuncSetAttribute(hmma_gemm<FEAT, false>,
                         cudaFuncAttributeMaxDynamicSharedMemorySize, SMEM_BYTES);

    pre_kernel<<<1408, 256>>>(x, a1, W1, w1t, W2, w2t);

    dim3 grid(FEAT / 128, B_ROWS / 64);   // (4, 64) = 256 CTAs, 2/SM
    hmma_gemm<DIN,  true ><<<grid, GT, SMEM_BYTES>>>(a1, w1t, b1, nullptr, h2);
    hmma_gemm<FEAT, false><<<grid, GT, SMEM_BYTES>>>(h2, w2t, b2, out, nullptr);
}